// round 1
// baseline (speedup 1.0000x reference)
#include <cuda_runtime.h>
#include <math.h>

#define NN   100000
#define FIN  128
#define HID  16
#define NC   2

// ---------------- scratch (device globals: no allocation allowed) ----------
__device__ float g_deg[NN];          // degree incl. self loop
__device__ float g_h1s[NN * HID];    // (x @ W1) * dinv[src]
__device__ float g_out1[NN * HID];   // layer-1 aggregation accumulator
__device__ float g_h2s[NN * NC];     // layer-2 pre-scaled messages
__device__ float g_out2[NN * NC];    // layer-2 aggregation accumulator

// ---------------- kernels --------------------------------------------------

__global__ void k_init_deg() {
    int i = blockIdx.x * blockDim.x + threadIdx.x;
    if (i < NN) g_deg[i] = 1.0f;     // self-loop contributes 1 to degree
}

__global__ void k_deg(const int* __restrict__ dst, int E) {
    int e = blockIdx.x * blockDim.x + threadIdx.x;
    if (e < E) atomicAdd(&g_deg[dst[e]], 1.0f);
}

// GEMM1: h1s = (x @ W1) * dinv ; out1 init = h1s * dinv (self-loop term)
// block = 256 threads = 16 nodes x 16 outputs
__global__ void k_gemm1(const float* __restrict__ x, const float* __restrict__ W1) {
    __shared__ float Ws[FIN * HID];      // 8 KB
    __shared__ float xs[16][FIN];        // 8 KB
    int tid = threadIdx.x;
    for (int t = tid; t < FIN * HID; t += 256) Ws[t] = W1[t];
    int node0 = blockIdx.x * 16;
    for (int t = tid; t < 16 * FIN; t += 256) {
        int r = t >> 7, c = t & 127;
        int gi = node0 + r;
        xs[r][c] = (gi < NN) ? x[(long long)gi * FIN + c] : 0.0f;
    }
    __syncthreads();
    int li = tid >> 4;       // local node 0..15
    int j  = tid & 15;       // output feature
    int i  = node0 + li;
    if (i >= NN) return;
    float s = 0.0f;
    #pragma unroll
    for (int k = 0; k < FIN; k++) s = fmaf(xs[li][k], Ws[k * HID + j], s);
    float dinv = rsqrtf(g_deg[i]);
    float hs = s * dinv;
    g_h1s[i * HID + j]  = hs;
    g_out1[i * HID + j] = hs * dinv;   // self-loop: h * dinv^2
}

// Aggregation layer 1: 16 lanes cooperate per edge (coalesced gather + atomics)
__global__ void k_agg1(const int* __restrict__ src, const int* __restrict__ dst, int E) {
    long long gt = (long long)blockIdx.x * blockDim.x + threadIdx.x;
    int e = (int)(gt >> 4);
    int j = (int)(gt & 15);
    if (e >= E) return;
    int s = src[e], d = dst[e];
    float v = g_h1s[s * HID + j] * rsqrtf(g_deg[d]);
    atomicAdd(&g_out1[d * HID + j], v);
}

// GEMM2: bias1 + relu + @W2, pre-scale by dinv, init out2 with self-loop term
__global__ void k_gemm2(const float* __restrict__ b1, const float* __restrict__ W2) {
    int i = blockIdx.x * blockDim.x + threadIdx.x;
    if (i >= NN) return;
    float acc0 = 0.0f, acc1 = 0.0f;
    #pragma unroll
    for (int j = 0; j < HID; j++) {
        float v = g_out1[i * HID + j] + b1[j];
        v = fmaxf(v, 0.0f);
        acc0 = fmaf(v, W2[j * NC + 0], acc0);
        acc1 = fmaf(v, W2[j * NC + 1], acc1);
    }
    float dinv = rsqrtf(g_deg[i]);
    float h0 = acc0 * dinv, h1 = acc1 * dinv;
    g_h2s[i * NC + 0]  = h0;
    g_h2s[i * NC + 1]  = h1;
    g_out2[i * NC + 0] = h0 * dinv;    // self-loop
    g_out2[i * NC + 1] = h1 * dinv;
}

// Aggregation layer 2: 2 lanes per edge
__global__ void k_agg2(const int* __restrict__ src, const int* __restrict__ dst, int E) {
    long long gt = (long long)blockIdx.x * blockDim.x + threadIdx.x;
    int e = (int)(gt >> 1);
    int c = (int)(gt & 1);
    if (e >= E) return;
    int s = src[e], d = dst[e];
    float v = g_h2s[s * NC + c] * rsqrtf(g_deg[d]);
    atomicAdd(&g_out2[d * NC + c], v);
}

// bias2 + log_softmax over 2 classes
__global__ void k_out(const float* __restrict__ b2, float* __restrict__ out) {
    int i = blockIdx.x * blockDim.x + threadIdx.x;
    if (i >= NN) return;
    float a = g_out2[i * 2 + 0] + b2[0];
    float b = g_out2[i * 2 + 1] + b2[1];
    float m = fmaxf(a, b);
    float lse = m + logf(expf(a - m) + expf(b - m));
    out[i * 2 + 0] = a - lse;
    out[i * 2 + 1] = b - lse;
}

// ---------------- launch ----------------------------------------------------

extern "C" void kernel_launch(void* const* d_in, const int* in_sizes, int n_in,
                              void* d_out, int out_size) {
    const float* x  = (const float*)d_in[0];
    const int*   ei = (const int*)  d_in[1];
    const float* W1 = (const float*)d_in[2];
    const float* b1 = (const float*)d_in[3];
    const float* W2 = (const float*)d_in[4];
    const float* b2 = (const float*)d_in[5];
    float* out = (float*)d_out;

    int E = in_sizes[1] / 2;
    const int* src = ei;        // edge_index[0]
    const int* dst = ei + E;    // edge_index[1]

    k_init_deg<<<(NN + 255) / 256, 256>>>();
    k_deg<<<(E + 255) / 256, 256>>>(dst, E);
    k_gemm1<<<(NN + 15) / 16, 256>>>(x, W1);

    long long t1 = (long long)E * HID;
    k_agg1<<<(unsigned)((t1 + 255) / 256), 256>>>(src, dst, E);

    k_gemm2<<<(NN + 255) / 256, 256>>>(b1, W2);

    long long t2 = (long long)E * NC;
    k_agg2<<<(unsigned)((t2 + 255) / 256), 256>>>(src, dst, E);

    k_out<<<(NN + 255) / 256, 256>>>(b2, out);
}

// round 2
// speedup vs baseline: 1.4027x; 1.4027x over previous
#include <cuda_runtime.h>
#include <math.h>

#define NN    100000
#define FIN   128
#define HID   16
#define NC    2
#define EMAX  3400000
#define SCAN_BLK 1024
#define NB_SCAN  ((NN + SCAN_BLK - 1) / SCAN_BLK)   // 98

// ---------------- scratch (device globals: no allocation allowed) ----------
__device__ int   g_cnt[NN];         // neighbor count (excl self loop)
__device__ int   g_off[NN + 1];     // CSR exclusive offsets
__device__ int   g_cursor[NN];      // scatter cursors
__device__ int   g_bsum[NB_SCAN];   // scan block sums
__device__ int   g_adj[EMAX];       // CSR adjacency (src ids grouped by dst)
__device__ float g_dinv[NN];        // 1/sqrt(deg) incl self loop
__device__ float g_h1s[NN * HID];   // (x @ W1) * dinv
__device__ float g_out1[NN * HID];  // layer-1 aggregated
__device__ float g_h2s[NN * NC];    // layer-2 pre-scaled messages

// ---------------- CSR build -------------------------------------------------

__global__ void k_zero() {
    int i = blockIdx.x * blockDim.x + threadIdx.x;
    if (i < NN) g_cnt[i] = 0;
}

__global__ void k_count(const int* __restrict__ dst, int E) {
    int e = blockIdx.x * blockDim.x + threadIdx.x;
    if (e < E) atomicAdd(&g_cnt[dst[e]], 1);
}

// block-local exclusive scan (Hillis-Steele in shared), emits block sums
__global__ void k_scanA() {
    __shared__ int s[SCAN_BLK];
    int tid = threadIdx.x;
    int i = blockIdx.x * SCAN_BLK + tid;
    int v = (i < NN) ? g_cnt[i] : 0;
    s[tid] = v;
    __syncthreads();
    #pragma unroll
    for (int o = 1; o < SCAN_BLK; o <<= 1) {
        int t = (tid >= o) ? s[tid - o] : 0;
        __syncthreads();
        s[tid] += t;
        __syncthreads();
    }
    if (i < NN) g_off[i] = s[tid] - v;          // exclusive within block
    if (tid == SCAN_BLK - 1) g_bsum[blockIdx.x] = s[tid];
}

__global__ void k_scanB() {                      // tiny: serial scan of 98 sums
    if (threadIdx.x == 0 && blockIdx.x == 0) {
        int run = 0;
        for (int b = 0; b < NB_SCAN; b++) {
            int t = g_bsum[b]; g_bsum[b] = run; run += t;
        }
    }
}

__global__ void k_scanC(int E) {
    int i = blockIdx.x * blockDim.x + threadIdx.x;
    if (i >= NN) return;
    int off = g_off[i] + g_bsum[i >> 10];
    g_off[i] = off;
    g_cursor[i] = off;
    g_dinv[i] = rsqrtf((float)g_cnt[i] + 1.0f);  // +1 self loop
    if (i == 0) g_off[NN] = E;
}

__global__ void k_scatter(const int* __restrict__ src, const int* __restrict__ dst, int E) {
    int e = blockIdx.x * blockDim.x + threadIdx.x;
    if (e >= E) return;
    int d = dst[e];
    int pos = atomicAdd(&g_cursor[d], 1);
    g_adj[pos] = src[e];
}

// ---------------- GEMM1: h1s = (x @ W1) * dinv ------------------------------
// block = 256 threads = 16 nodes x 16 outputs
__global__ void k_gemm1(const float* __restrict__ x, const float* __restrict__ W1) {
    __shared__ float Ws[FIN * HID];
    __shared__ float xs[16][FIN];
    int tid = threadIdx.x;
    for (int t = tid; t < FIN * HID; t += 256) Ws[t] = W1[t];
    int node0 = blockIdx.x * 16;
    for (int t = tid; t < 16 * FIN; t += 256) {
        int r = t >> 7, c = t & 127;
        int gi = node0 + r;
        xs[r][c] = (gi < NN) ? x[(long long)gi * FIN + c] : 0.0f;
    }
    __syncthreads();
    int li = tid >> 4, j = tid & 15;
    int i = node0 + li;
    if (i >= NN) return;
    float s = 0.0f;
    #pragma unroll
    for (int k = 0; k < FIN; k++) s = fmaf(xs[li][k], Ws[k * HID + j], s);
    g_h1s[i * HID + j] = s * g_dinv[i];
}

// ---------------- Aggregation 1 (pull, no atomics) --------------------------
// 16 lanes per node; lane j accumulates feature j over the node's edge list.
__global__ void k_agg1g() {
    int tid = threadIdx.x;
    int node = blockIdx.x * 16 + (tid >> 4);
    int j = tid & 15;
    if (node >= NN) return;
    int beg = g_off[node], end = g_off[node + 1];
    float acc = 0.0f;
    int k = beg;
    for (; k + 4 <= end; k += 4) {                // unroll for MLP
        int s0 = g_adj[k], s1 = g_adj[k + 1], s2 = g_adj[k + 2], s3 = g_adj[k + 3];
        float a = g_h1s[s0 * HID + j];
        float b = g_h1s[s1 * HID + j];
        float c = g_h1s[s2 * HID + j];
        float d = g_h1s[s3 * HID + j];
        acc += (a + b) + (c + d);
    }
    for (; k < end; k++) acc += g_h1s[g_adj[k] * HID + j];
    float dv = g_dinv[node];
    g_out1[node * HID + j] = dv * (acc + g_h1s[node * HID + j]);  // + self loop
}

// ---------------- GEMM2: relu(out1+b1) @ W2, pre-scale by dinv --------------
__global__ void k_gemm2(const float* __restrict__ b1, const float* __restrict__ W2) {
    int i = blockIdx.x * blockDim.x + threadIdx.x;
    if (i >= NN) return;
    float acc0 = 0.0f, acc1 = 0.0f;
    #pragma unroll
    for (int j = 0; j < HID; j++) {
        float v = fmaxf(g_out1[i * HID + j] + b1[j], 0.0f);
        acc0 = fmaf(v, W2[j * NC + 0], acc0);
        acc1 = fmaf(v, W2[j * NC + 1], acc1);
    }
    float dv = g_dinv[i];
    ((float2*)g_h2s)[i] = make_float2(acc0 * dv, acc1 * dv);
}

// ---------------- Aggregation 2 + bias + log_softmax (fused) ----------------
__global__ void k_agg2g(const float* __restrict__ b2, float* __restrict__ out) {
    int i = blockIdx.x * blockDim.x + threadIdx.x;
    if (i >= NN) return;
    int beg = g_off[i], end = g_off[i + 1];
    float a0 = 0.0f, a1 = 0.0f;
    const float2* h2 = (const float2*)g_h2s;
    int k = beg;
    for (; k + 4 <= end; k += 4) {
        float2 v0 = h2[g_adj[k]];
        float2 v1 = h2[g_adj[k + 1]];
        float2 v2 = h2[g_adj[k + 2]];
        float2 v3 = h2[g_adj[k + 3]];
        a0 += (v0.x + v1.x) + (v2.x + v3.x);
        a1 += (v0.y + v1.y) + (v2.y + v3.y);
    }
    for (; k < end; k++) { float2 v = h2[g_adj[k]]; a0 += v.x; a1 += v.y; }
    float dv = g_dinv[i];
    float2 self = h2[i];
    float A = dv * (a0 + self.x) + b2[0];
    float B = dv * (a1 + self.y) + b2[1];
    float m = fmaxf(A, B);
    float lse = m + logf(expf(A - m) + expf(B - m));
    ((float2*)out)[i] = make_float2(A - lse, B - lse);
}

// ---------------- launch ----------------------------------------------------

extern "C" void kernel_launch(void* const* d_in, const int* in_sizes, int n_in,
                              void* d_out, int out_size) {
    const float* x  = (const float*)d_in[0];
    const int*   ei = (const int*)  d_in[1];
    const float* W1 = (const float*)d_in[2];
    const float* b1 = (const float*)d_in[3];
    const float* W2 = (const float*)d_in[4];
    const float* b2 = (const float*)d_in[5];
    float* out = (float*)d_out;

    int E = in_sizes[1] / 2;
    const int* src = ei;
    const int* dst = ei + E;

    k_zero   <<<(NN + 255) / 256, 256>>>();
    k_count  <<<(E + 255) / 256, 256>>>(dst, E);
    k_scanA  <<<NB_SCAN, SCAN_BLK>>>();
    k_scanB  <<<1, 32>>>();
    k_scanC  <<<(NN + 255) / 256, 256>>>(E);
    k_scatter<<<(E + 255) / 256, 256>>>(src, dst, E);
    k_gemm1  <<<(NN + 15) / 16, 256>>>(x, W1);
    k_agg1g  <<<(NN + 15) / 16, 256>>>();
    k_gemm2  <<<(NN + 255) / 256, 256>>>(b1, W2);
    k_agg2g  <<<(NN + 255) / 256, 256>>>(b2, out);
}

// round 3
// speedup vs baseline: 1.7325x; 1.2351x over previous
#include <cuda_runtime.h>
#include <math.h>

#define NN    100000
#define FIN   128
#define HID   16
#define NC    2
#define EMAX  3400000
#define SCAN_BLK 1024
#define NB_SCAN  ((NN + SCAN_BLK - 1) / SCAN_BLK)   // 98

// ---------------- scratch (device globals: no allocation allowed) ----------
__device__ int   g_cnt[NN];
__device__ int   g_off[NN + 1];
__device__ int   g_cursor[NN];
__device__ int   g_bsum[NB_SCAN];
__device__ int   g_adj[EMAX];
__device__ float g_dinv[NN];
__device__ float g_h1s[NN * HID];
__device__ float g_out1[NN * HID];
__device__ float g_h2s[NN * NC];

// ---------------- CSR build -------------------------------------------------

__global__ void k_zero() {
    int i = blockIdx.x * blockDim.x + threadIdx.x;
    if (i < NN) g_cnt[i] = 0;
}

__global__ void k_count(const int* __restrict__ dst, int E) {
    int e = blockIdx.x * blockDim.x + threadIdx.x;
    if (e < E) atomicAdd(&g_cnt[dst[e]], 1);
}

__global__ void k_scanA() {
    __shared__ int s[SCAN_BLK];
    int tid = threadIdx.x;
    int i = blockIdx.x * SCAN_BLK + tid;
    int v = (i < NN) ? g_cnt[i] : 0;
    s[tid] = v;
    __syncthreads();
    #pragma unroll
    for (int o = 1; o < SCAN_BLK; o <<= 1) {
        int t = (tid >= o) ? s[tid - o] : 0;
        __syncthreads();
        s[tid] += t;
        __syncthreads();
    }
    if (i < NN) g_off[i] = s[tid] - v;           // exclusive within block
    if (tid == SCAN_BLK - 1) g_bsum[blockIdx.x] = s[tid];
}

// scanC: every block redundantly scans the 98 block sums (cheap), then
// finalizes offsets / cursors / dinv. Eliminates the serial scanB kernel.
__global__ void k_scanC(int E) {
    __shared__ int sbs[128];
    int t = threadIdx.x;                          // 256 threads
    if (t < 128) sbs[t] = (t < NB_SCAN) ? g_bsum[t] : 0;
    __syncthreads();
    #pragma unroll
    for (int o = 1; o < 128; o <<= 1) {
        int v = (t < 128 && t >= o) ? sbs[t - o] : 0;
        __syncthreads();
        if (t < 128) sbs[t] += v;                 // inclusive scan of block sums
        __syncthreads();
    }
    int i = blockIdx.x * 256 + t;
    if (i >= NN) return;
    int blk = i >> 10;
    int base = (blk > 0) ? sbs[blk - 1] : 0;
    int off = g_off[i] + base;
    g_off[i] = off;
    g_cursor[i] = off;
    g_dinv[i] = rsqrtf((float)g_cnt[i] + 1.0f);   // +1 self loop
    if (i == 0) g_off[NN] = E;
}

__global__ void k_scatter(const int* __restrict__ src, const int* __restrict__ dst, int E) {
    int e = blockIdx.x * blockDim.x + threadIdx.x;
    if (e >= E) return;
    int d = dst[e];
    int pos = atomicAdd(&g_cursor[d], 1);
    g_adj[pos] = src[e];
}

// ---------------- GEMM1 (register-tiled): h1s = (x @ W1) * dinv -------------
// 128 threads = 128 nodes; each thread owns all 16 outputs in registers.
// Per k: 1 LDS (x) + 4 broadcast LDS.128 (W row) for 16 FMAs.
__global__ void k_gemm1(const float* __restrict__ x, const float* __restrict__ W1) {
    __shared__ float xs[128][33];                 // 32-col chunk, padded
    __shared__ float ws[32][16];
    int tid = threadIdx.x;
    int node0 = blockIdx.x * 128;
    int node = node0 + tid;
    float acc[16];
    #pragma unroll
    for (int j = 0; j < 16; j++) acc[j] = 0.0f;

    for (int kc = 0; kc < FIN; kc += 32) {
        __syncthreads();
        for (int it = 0; it < 32; it++) {         // x chunk, coalesced rows
            int idx = it * 128 + tid;
            int r = idx >> 5, c = idx & 31;
            int gi = node0 + r;
            xs[r][c] = (gi < NN) ? x[(size_t)gi * FIN + kc + c] : 0.0f;
        }
        #pragma unroll
        for (int it = 0; it < 4; it++) {          // W chunk, contiguous
            int idx = it * 128 + tid;
            ((float*)ws)[idx] = W1[kc * HID + idx];
        }
        __syncthreads();
        #pragma unroll
        for (int k = 0; k < 32; k++) {
            float xv = xs[tid][k];
            const float4* wrow = (const float4*)&ws[k][0];
            float4 w0 = wrow[0], w1 = wrow[1], w2 = wrow[2], w3 = wrow[3];
            acc[0]  = fmaf(xv, w0.x, acc[0]);
            acc[1]  = fmaf(xv, w0.y, acc[1]);
            acc[2]  = fmaf(xv, w0.z, acc[2]);
            acc[3]  = fmaf(xv, w0.w, acc[3]);
            acc[4]  = fmaf(xv, w1.x, acc[4]);
            acc[5]  = fmaf(xv, w1.y, acc[5]);
            acc[6]  = fmaf(xv, w1.z, acc[6]);
            acc[7]  = fmaf(xv, w1.w, acc[7]);
            acc[8]  = fmaf(xv, w2.x, acc[8]);
            acc[9]  = fmaf(xv, w2.y, acc[9]);
            acc[10] = fmaf(xv, w2.z, acc[10]);
            acc[11] = fmaf(xv, w2.w, acc[11]);
            acc[12] = fmaf(xv, w3.x, acc[12]);
            acc[13] = fmaf(xv, w3.y, acc[13]);
            acc[14] = fmaf(xv, w3.z, acc[14]);
            acc[15] = fmaf(xv, w3.w, acc[15]);
        }
    }
    if (node >= NN) return;
    float dv = g_dinv[node];
    float4* o = (float4*)&g_h1s[node * HID];
    o[0] = make_float4(acc[0] * dv,  acc[1] * dv,  acc[2] * dv,  acc[3] * dv);
    o[1] = make_float4(acc[4] * dv,  acc[5] * dv,  acc[6] * dv,  acc[7] * dv);
    o[2] = make_float4(acc[8] * dv,  acc[9] * dv,  acc[10] * dv, acc[11] * dv);
    o[3] = make_float4(acc[12] * dv, acc[13] * dv, acc[14] * dv, acc[15] * dv);
}

// ---------------- Aggregation 1 (pull, no atomics) --------------------------
__global__ void k_agg1g() {
    int tid = threadIdx.x;
    int node = blockIdx.x * 16 + (tid >> 4);
    int j = tid & 15;
    if (node >= NN) return;
    int beg = g_off[node], end = g_off[node + 1];
    float acc = 0.0f;
    int k = beg;
    for (; k + 8 <= end; k += 8) {
        int s0 = g_adj[k],     s1 = g_adj[k + 1], s2 = g_adj[k + 2], s3 = g_adj[k + 3];
        int s4 = g_adj[k + 4], s5 = g_adj[k + 5], s6 = g_adj[k + 6], s7 = g_adj[k + 7];
        float a0 = g_h1s[s0 * HID + j];
        float a1 = g_h1s[s1 * HID + j];
        float a2 = g_h1s[s2 * HID + j];
        float a3 = g_h1s[s3 * HID + j];
        float a4 = g_h1s[s4 * HID + j];
        float a5 = g_h1s[s5 * HID + j];
        float a6 = g_h1s[s6 * HID + j];
        float a7 = g_h1s[s7 * HID + j];
        acc += ((a0 + a1) + (a2 + a3)) + ((a4 + a5) + (a6 + a7));
    }
    for (; k < end; k++) acc += g_h1s[g_adj[k] * HID + j];
    g_out1[node * HID + j] = g_dinv[node] * (acc + g_h1s[node * HID + j]);
}

// ---------------- GEMM2 -----------------------------------------------------
__global__ void k_gemm2(const float* __restrict__ b1, const float* __restrict__ W2) {
    int i = blockIdx.x * blockDim.x + threadIdx.x;
    if (i >= NN) return;
    float acc0 = 0.0f, acc1 = 0.0f;
    #pragma unroll
    for (int j = 0; j < HID; j++) {
        float v = fmaxf(g_out1[i * HID + j] + b1[j], 0.0f);
        acc0 = fmaf(v, W2[j * NC + 0], acc0);
        acc1 = fmaf(v, W2[j * NC + 1], acc1);
    }
    float dv = g_dinv[i];
    ((float2*)g_h2s)[i] = make_float2(acc0 * dv, acc1 * dv);
}

// ---------------- Aggregation 2 + bias + log_softmax ------------------------
__global__ void k_agg2g(const float* __restrict__ b2, float* __restrict__ out) {
    int i = blockIdx.x * blockDim.x + threadIdx.x;
    if (i >= NN) return;
    int beg = g_off[i], end = g_off[i + 1];
    float a0 = 0.0f, a1 = 0.0f;
    const float2* h2 = (const float2*)g_h2s;
    int k = beg;
    for (; k + 4 <= end; k += 4) {
        float2 v0 = h2[g_adj[k]];
        float2 v1 = h2[g_adj[k + 1]];
        float2 v2 = h2[g_adj[k + 2]];
        float2 v3 = h2[g_adj[k + 3]];
        a0 += (v0.x + v1.x) + (v2.x + v3.x);
        a1 += (v0.y + v1.y) + (v2.y + v3.y);
    }
    for (; k < end; k++) { float2 v = h2[g_adj[k]]; a0 += v.x; a1 += v.y; }
    float dv = g_dinv[i];
    float2 self = h2[i];
    float A = dv * (a0 + self.x) + b2[0];
    float B = dv * (a1 + self.y) + b2[1];
    float m = fmaxf(A, B);
    float lse = m + logf(expf(A - m) + expf(B - m));
    ((float2*)out)[i] = make_float2(A - lse, B - lse);
}

// ---------------- launch ----------------------------------------------------

extern "C" void kernel_launch(void* const* d_in, const int* in_sizes, int n_in,
                              void* d_out, int out_size) {
    const float* x  = (const float*)d_in[0];
    const int*   ei = (const int*)  d_in[1];
    const float* W1 = (const float*)d_in[2];
    const float* b1 = (const float*)d_in[3];
    const float* W2 = (const float*)d_in[4];
    const float* b2 = (const float*)d_in[5];
    float* out = (float*)d_out;

    int E = in_sizes[1] / 2;
    const int* src = ei;
    const int* dst = ei + E;

    k_zero   <<<(NN + 255) / 256, 256>>>();
    k_count  <<<(E + 255) / 256, 256>>>(dst, E);
    k_scanA  <<<NB_SCAN, SCAN_BLK>>>();
    k_scanC  <<<(NN + 255) / 256, 256>>>(E);
    k_scatter<<<(E + 255) / 256, 256>>>(src, dst, E);
    k_gemm1  <<<(NN + 127) / 128, 128>>>(x, W1);
    k_agg1g  <<<(NN + 15) / 16, 256>>>();
    k_gemm2  <<<(NN + 255) / 256, 256>>>(b1, W2);
    k_agg2g  <<<(NN + 255) / 256, 256>>>(b2, out);
}

// round 4
// speedup vs baseline: 1.8166x; 1.0485x over previous
#include <cuda_runtime.h>
#include <cuda_fp16.h>
#include <math.h>

#define NN    100000
#define FIN   128
#define HID   16
#define NC    2
#define EMAX  3400000
#define SCAN_BLK 1024
#define NB_SCAN  ((NN + SCAN_BLK - 1) / SCAN_BLK)   // 98

// ---------------- scratch (device globals: no allocation allowed) ----------
__device__ int    g_cnt[NN];
__device__ int    g_off[NN + 1];
__device__ int    g_cursor[NN];
__device__ int    g_bsum[NB_SCAN];
__device__ int    g_adj[EMAX];
__device__ float  g_dinv[NN];
__device__ __half g_h1s[NN * HID];   // fp16: 32B per node row = 1 L2 sector
__device__ float  g_h2s[NN * NC];

// ---------------- CSR build -------------------------------------------------

__global__ void k_zero() {
    int i = blockIdx.x * blockDim.x + threadIdx.x;
    if (i < NN) g_cnt[i] = 0;
}

__global__ void k_count(const int* __restrict__ dst, int E) {
    int e = blockIdx.x * blockDim.x + threadIdx.x;
    if (e < E) atomicAdd(&g_cnt[dst[e]], 1);
}

// warp-shuffle block scan (exclusive offsets within block + block sum)
__global__ void k_scanA() {
    __shared__ int wsum[32];
    int tid = threadIdx.x;
    int i = blockIdx.x * SCAN_BLK + tid;
    int v = (i < NN) ? g_cnt[i] : 0;
    int lane = tid & 31, wid = tid >> 5;
    int inc = v;
    #pragma unroll
    for (int o = 1; o < 32; o <<= 1) {
        int t = __shfl_up_sync(0xffffffffu, inc, o);
        if (lane >= o) inc += t;
    }
    if (lane == 31) wsum[wid] = inc;
    __syncthreads();
    if (wid == 0) {
        int s = wsum[lane];
        #pragma unroll
        for (int o = 1; o < 32; o <<= 1) {
            int t = __shfl_up_sync(0xffffffffu, s, o);
            if (lane >= o) s += t;
        }
        wsum[lane] = s;
    }
    __syncthreads();
    int base = (wid > 0) ? wsum[wid - 1] : 0;
    if (i < NN) g_off[i] = base + inc - v;        // exclusive
    if (tid == SCAN_BLK - 1) g_bsum[blockIdx.x] = base + inc;
}

// every block redundantly scans the 98 block sums, then finalizes
__global__ void k_scanC(int E) {
    __shared__ int sbs[128];
    int t = threadIdx.x;                          // 256 threads
    if (t < 128) sbs[t] = (t < NB_SCAN) ? g_bsum[t] : 0;
    __syncthreads();
    #pragma unroll
    for (int o = 1; o < 128; o <<= 1) {
        int v = (t < 128 && t >= o) ? sbs[t - o] : 0;
        __syncthreads();
        if (t < 128) sbs[t] += v;
        __syncthreads();
    }
    int i = blockIdx.x * 256 + t;
    if (i >= NN) return;
    int blk = i >> 10;
    int base = (blk > 0) ? sbs[blk - 1] : 0;
    int off = g_off[i] + base;
    g_off[i] = off;
    g_cursor[i] = off;
    g_dinv[i] = rsqrtf((float)g_cnt[i] + 1.0f);   // +1 self loop
    if (i == 0) g_off[NN] = E;
}

__global__ void k_scatter(const int* __restrict__ src, const int* __restrict__ dst, int E) {
    int e = blockIdx.x * blockDim.x + threadIdx.x;
    if (e >= E) return;
    int d = dst[e];
    int pos = atomicAdd(&g_cursor[d], 1);
    g_adj[pos] = src[e];
}

// ---------------- GEMM1 (register-tiled): h1s = fp16((x @ W1) * dinv) -------
__global__ void k_gemm1(const float* __restrict__ x, const float* __restrict__ W1) {
    __shared__ float xs[128][33];
    __shared__ float ws[32][16];
    int tid = threadIdx.x;
    int node0 = blockIdx.x * 128;
    int node = node0 + tid;
    float acc[16];
    #pragma unroll
    for (int j = 0; j < 16; j++) acc[j] = 0.0f;

    for (int kc = 0; kc < FIN; kc += 32) {
        __syncthreads();
        for (int it = 0; it < 32; it++) {
            int idx = it * 128 + tid;
            int r = idx >> 5, c = idx & 31;
            int gi = node0 + r;
            xs[r][c] = (gi < NN) ? x[(size_t)gi * FIN + kc + c] : 0.0f;
        }
        #pragma unroll
        for (int it = 0; it < 4; it++) {
            int idx = it * 128 + tid;
            ((float*)ws)[idx] = W1[kc * HID + idx];
        }
        __syncthreads();
        #pragma unroll
        for (int k = 0; k < 32; k++) {
            float xv = xs[tid][k];
            const float4* wrow = (const float4*)&ws[k][0];
            float4 w0 = wrow[0], w1 = wrow[1], w2 = wrow[2], w3 = wrow[3];
            acc[0]  = fmaf(xv, w0.x, acc[0]);
            acc[1]  = fmaf(xv, w0.y, acc[1]);
            acc[2]  = fmaf(xv, w0.z, acc[2]);
            acc[3]  = fmaf(xv, w0.w, acc[3]);
            acc[4]  = fmaf(xv, w1.x, acc[4]);
            acc[5]  = fmaf(xv, w1.y, acc[5]);
            acc[6]  = fmaf(xv, w1.z, acc[6]);
            acc[7]  = fmaf(xv, w1.w, acc[7]);
            acc[8]  = fmaf(xv, w2.x, acc[8]);
            acc[9]  = fmaf(xv, w2.y, acc[9]);
            acc[10] = fmaf(xv, w2.z, acc[10]);
            acc[11] = fmaf(xv, w2.w, acc[11]);
            acc[12] = fmaf(xv, w3.x, acc[12]);
            acc[13] = fmaf(xv, w3.y, acc[13]);
            acc[14] = fmaf(xv, w3.z, acc[14]);
            acc[15] = fmaf(xv, w3.w, acc[15]);
        }
    }
    if (node >= NN) return;
    float dv = g_dinv[node];
    __half2 h[8];
    #pragma unroll
    for (int j = 0; j < 8; j++)
        h[j] = __floats2half2_rn(acc[2 * j] * dv, acc[2 * j + 1] * dv);
    uint4* o = (uint4*)&g_h1s[node * HID];
    o[0] = *(uint4*)&h[0];
    o[1] = *(uint4*)&h[4];
}

// ---------------- Fused Aggregation1 + ReLU + GEMM2 -------------------------
// 8 lanes per node; lane ln owns feature pair (2ln, 2ln+1) as half2.
__global__ void k_agg1f(const float* __restrict__ b1, const float* __restrict__ W2) {
    int tid = threadIdx.x;
    int node = blockIdx.x * 32 + (tid >> 3);
    int ln = tid & 7;
    if (node >= NN) return;
    const __half2* h1 = (const __half2*)g_h1s;    // [NN*8]
    int beg = g_off[node], end = g_off[node + 1];
    float a0 = 0.0f, a1 = 0.0f;
    int k = beg;
    for (; k + 8 <= end; k += 8) {
        int s0 = g_adj[k],     s1 = g_adj[k + 1], s2 = g_adj[k + 2], s3 = g_adj[k + 3];
        int s4 = g_adj[k + 4], s5 = g_adj[k + 5], s6 = g_adj[k + 6], s7 = g_adj[k + 7];
        float2 v0 = __half22float2(h1[s0 * 8 + ln]);
        float2 v1 = __half22float2(h1[s1 * 8 + ln]);
        float2 v2 = __half22float2(h1[s2 * 8 + ln]);
        float2 v3 = __half22float2(h1[s3 * 8 + ln]);
        float2 v4 = __half22float2(h1[s4 * 8 + ln]);
        float2 v5 = __half22float2(h1[s5 * 8 + ln]);
        float2 v6 = __half22float2(h1[s6 * 8 + ln]);
        float2 v7 = __half22float2(h1[s7 * 8 + ln]);
        a0 += ((v0.x + v1.x) + (v2.x + v3.x)) + ((v4.x + v5.x) + (v6.x + v7.x));
        a1 += ((v0.y + v1.y) + (v2.y + v3.y)) + ((v4.y + v5.y) + (v6.y + v7.y));
    }
    for (; k < end; k++) {
        float2 v = __half22float2(h1[g_adj[k] * 8 + ln]);
        a0 += v.x; a1 += v.y;
    }
    float2 self = __half22float2(h1[node * 8 + ln]);
    float dv = g_dinv[node];
    float o0 = dv * (a0 + self.x);
    float o1 = dv * (a1 + self.y);
    int f0 = ln * 2, f1 = f0 + 1;
    float v0 = fmaxf(o0 + b1[f0], 0.0f);
    float v1 = fmaxf(o1 + b1[f1], 0.0f);
    float c0 = fmaf(v0, W2[f0 * 2 + 0], v1 * W2[f1 * 2 + 0]);
    float c1 = fmaf(v0, W2[f0 * 2 + 1], v1 * W2[f1 * 2 + 1]);
    #pragma unroll
    for (int m = 4; m >= 1; m >>= 1) {
        c0 += __shfl_xor_sync(0xffffffffu, c0, m, 8);
        c1 += __shfl_xor_sync(0xffffffffu, c1, m, 8);
    }
    if (ln == 0) ((float2*)g_h2s)[node] = make_float2(c0 * dv, c1 * dv);
}

// ---------------- Aggregation 2 + bias + log_softmax ------------------------
__global__ void k_agg2g(const float* __restrict__ b2, float* __restrict__ out) {
    int i = blockIdx.x * blockDim.x + threadIdx.x;
    if (i >= NN) return;
    int beg = g_off[i], end = g_off[i + 1];
    float a0 = 0.0f, a1 = 0.0f;
    const float2* h2 = (const float2*)g_h2s;
    int k = beg;
    for (; k + 4 <= end; k += 4) {
        float2 v0 = h2[g_adj[k]];
        float2 v1 = h2[g_adj[k + 1]];
        float2 v2 = h2[g_adj[k + 2]];
        float2 v3 = h2[g_adj[k + 3]];
        a0 += (v0.x + v1.x) + (v2.x + v3.x);
        a1 += (v0.y + v1.y) + (v2.y + v3.y);
    }
    for (; k < end; k++) { float2 v = h2[g_adj[k]]; a0 += v.x; a1 += v.y; }
    float dv = g_dinv[i];
    float2 self = h2[i];
    float A = dv * (a0 + self.x) + b2[0];
    float B = dv * (a1 + self.y) + b2[1];
    float m = fmaxf(A, B);
    float lse = m + logf(expf(A - m) + expf(B - m));
    ((float2*)out)[i] = make_float2(A - lse, B - lse);
}

// ---------------- launch ----------------------------------------------------

extern "C" void kernel_launch(void* const* d_in, const int* in_sizes, int n_in,
                              void* d_out, int out_size) {
    const float* x  = (const float*)d_in[0];
    const int*   ei = (const int*)  d_in[1];
    const float* W1 = (const float*)d_in[2];
    const float* b1 = (const float*)d_in[3];
    const float* W2 = (const float*)d_in[4];
    const float* b2 = (const float*)d_in[5];
    float* out = (float*)d_out;

    int E = in_sizes[1] / 2;
    const int* src = ei;
    const int* dst = ei + E;

    k_zero   <<<(NN + 255) / 256, 256>>>();
    k_count  <<<(E + 255) / 256, 256>>>(dst, E);
    k_scanA  <<<NB_SCAN, SCAN_BLK>>>();
    k_scanC  <<<(NN + 255) / 256, 256>>>(E);
    k_scatter<<<(E + 255) / 256, 256>>>(src, dst, E);
    k_gemm1  <<<(NN + 127) / 128, 128>>>(x, W1);
    k_agg1f  <<<(NN + 31) / 32, 256>>>(b1, W2);
    k_agg2g  <<<(NN + 255) / 256, 256>>>(b2, out);
}

// round 5
// speedup vs baseline: 1.8956x; 1.0435x over previous
#include <cuda_runtime.h>
#include <cuda_fp16.h>
#include <math.h>

#define NN    100000
#define FIN   128
#define HID   16
#define NC    2
#define EMAX  3400000
#define OFF_BLK 1024
#define NB_OFF  ((NN + OFF_BLK - 1) / OFF_BLK)   // 98

// ---------------- scratch (device globals: no allocation allowed) ----------
__device__ int    g_cnt[NN];
__device__ int    g_beg[NN];
__device__ int    g_cursor[NN];
__device__ int    g_total;
__device__ int    g_adj[EMAX];
__device__ float  g_dinv[NN];
__device__ __half g_h1s[NN * HID];   // 32B per node row = 1 L2 sector
__device__ float  g_h2s[NN * NC];

// ---------------- CSR build -------------------------------------------------

__global__ void k_count(const int* __restrict__ dst, int E) {
    int t = blockIdx.x * blockDim.x + threadIdx.x;
    if (t == 0) g_total = 0;                      // consumed only by k_offsets
    int e = t * 4;
    if (e + 3 < E) {
        int4 d = *(const int4*)&dst[e];
        atomicAdd(&g_cnt[d.x], 1);
        atomicAdd(&g_cnt[d.y], 1);
        atomicAdd(&g_cnt[d.z], 1);
        atomicAdd(&g_cnt[d.w], 1);
    } else {
        for (int k = e; k < E; k++) atomicAdd(&g_cnt[dst[k]], 1);
    }
}

// offsets via block scan + single atomic block-base (no global scan needed:
// CSR buckets only need to be disjoint, not ordered by node id)
__global__ void k_offsets() {
    __shared__ int wsum[32];
    __shared__ int base_sh;
    int tid = threadIdx.x;
    int i = blockIdx.x * OFF_BLK + tid;
    int v = (i < NN) ? g_cnt[i] : 0;
    int lane = tid & 31, wid = tid >> 5;
    int inc = v;
    #pragma unroll
    for (int o = 1; o < 32; o <<= 1) {
        int t = __shfl_up_sync(0xffffffffu, inc, o);
        if (lane >= o) inc += t;
    }
    if (lane == 31) wsum[wid] = inc;
    __syncthreads();
    if (wid == 0) {
        int s = wsum[lane];
        #pragma unroll
        for (int o = 1; o < 32; o <<= 1) {
            int t = __shfl_up_sync(0xffffffffu, s, o);
            if (lane >= o) s += t;
        }
        wsum[lane] = s;
        if (lane == 31) base_sh = atomicAdd(&g_total, s);   // block base
    }
    __syncthreads();
    if (i >= NN) return;
    int wbase = (wid > 0) ? wsum[wid - 1] : 0;
    int beg = base_sh + wbase + inc - v;          // exclusive within block
    g_beg[i] = beg;
    g_cursor[i] = beg;
    g_dinv[i] = rsqrtf((float)v + 1.0f);          // +1 self loop
}

__global__ void k_scatter(const int* __restrict__ src, const int* __restrict__ dst, int E) {
    int t = blockIdx.x * blockDim.x + threadIdx.x;
    int e = t * 4;
    if (e + 3 < E) {
        int4 s = *(const int4*)&src[e];
        int4 d = *(const int4*)&dst[e];
        int p0 = atomicAdd(&g_cursor[d.x], 1);
        int p1 = atomicAdd(&g_cursor[d.y], 1);
        int p2 = atomicAdd(&g_cursor[d.z], 1);
        int p3 = atomicAdd(&g_cursor[d.w], 1);
        g_adj[p0] = s.x;
        g_adj[p1] = s.y;
        g_adj[p2] = s.z;
        g_adj[p3] = s.w;
    } else {
        for (int k = e; k < E; k++) {
            int pos = atomicAdd(&g_cursor[dst[k]], 1);
            g_adj[pos] = src[k];
        }
    }
}

// ---------------- GEMM1 (register-tiled): h1s = fp16((x @ W1) * dinv) -------
__global__ void k_gemm1(const float* __restrict__ x, const float* __restrict__ W1) {
    __shared__ float xs[128][33];
    __shared__ float ws[32][16];
    int tid = threadIdx.x;
    int node0 = blockIdx.x * 128;
    int node = node0 + tid;
    float acc[16];
    #pragma unroll
    for (int j = 0; j < 16; j++) acc[j] = 0.0f;

    for (int kc = 0; kc < FIN; kc += 32) {
        __syncthreads();
        for (int it = 0; it < 32; it++) {
            int idx = it * 128 + tid;
            int r = idx >> 5, c = idx & 31;
            int gi = node0 + r;
            xs[r][c] = (gi < NN) ? x[(size_t)gi * FIN + kc + c] : 0.0f;
        }
        #pragma unroll
        for (int it = 0; it < 4; it++) {
            int idx = it * 128 + tid;
            ((float*)ws)[idx] = W1[kc * HID + idx];
        }
        __syncthreads();
        #pragma unroll
        for (int k = 0; k < 32; k++) {
            float xv = xs[tid][k];
            const float4* wrow = (const float4*)&ws[k][0];
            float4 w0 = wrow[0], w1 = wrow[1], w2 = wrow[2], w3 = wrow[3];
            acc[0]  = fmaf(xv, w0.x, acc[0]);
            acc[1]  = fmaf(xv, w0.y, acc[1]);
            acc[2]  = fmaf(xv, w0.z, acc[2]);
            acc[3]  = fmaf(xv, w0.w, acc[3]);
            acc[4]  = fmaf(xv, w1.x, acc[4]);
            acc[5]  = fmaf(xv, w1.y, acc[5]);
            acc[6]  = fmaf(xv, w1.z, acc[6]);
            acc[7]  = fmaf(xv, w1.w, acc[7]);
            acc[8]  = fmaf(xv, w2.x, acc[8]);
            acc[9]  = fmaf(xv, w2.y, acc[9]);
            acc[10] = fmaf(xv, w2.z, acc[10]);
            acc[11] = fmaf(xv, w2.w, acc[11]);
            acc[12] = fmaf(xv, w3.x, acc[12]);
            acc[13] = fmaf(xv, w3.y, acc[13]);
            acc[14] = fmaf(xv, w3.z, acc[14]);
            acc[15] = fmaf(xv, w3.w, acc[15]);
        }
    }
    if (node >= NN) return;
    float dv = g_dinv[node];
    __half2 h[8];
    #pragma unroll
    for (int j = 0; j < 8; j++)
        h[j] = __floats2half2_rn(acc[2 * j] * dv, acc[2 * j + 1] * dv);
    uint4* o = (uint4*)&g_h1s[node * HID];
    o[0] = *(uint4*)&h[0];
    o[1] = *(uint4*)&h[4];
}

// ---------------- Fused Aggregation1 + ReLU + GEMM2 -------------------------
// 8 lanes per node; lane ln owns feature pair (2ln, 2ln+1) as half2.
__global__ void k_agg1f(const float* __restrict__ b1, const float* __restrict__ W2) {
    int tid = threadIdx.x;
    int node = blockIdx.x * 32 + (tid >> 3);
    int ln = tid & 7;
    if (node >= NN) return;
    const __half2* h1 = (const __half2*)g_h1s;    // [NN*8]
    int beg = g_beg[node];
    int end = beg + g_cnt[node];
    float a0 = 0.0f, a1 = 0.0f;
    int k = beg;
    for (; k + 8 <= end; k += 8) {
        int s0 = g_adj[k],     s1 = g_adj[k + 1], s2 = g_adj[k + 2], s3 = g_adj[k + 3];
        int s4 = g_adj[k + 4], s5 = g_adj[k + 5], s6 = g_adj[k + 6], s7 = g_adj[k + 7];
        float2 v0 = __half22float2(h1[s0 * 8 + ln]);
        float2 v1 = __half22float2(h1[s1 * 8 + ln]);
        float2 v2 = __half22float2(h1[s2 * 8 + ln]);
        float2 v3 = __half22float2(h1[s3 * 8 + ln]);
        float2 v4 = __half22float2(h1[s4 * 8 + ln]);
        float2 v5 = __half22float2(h1[s5 * 8 + ln]);
        float2 v6 = __half22float2(h1[s6 * 8 + ln]);
        float2 v7 = __half22float2(h1[s7 * 8 + ln]);
        a0 += ((v0.x + v1.x) + (v2.x + v3.x)) + ((v4.x + v5.x) + (v6.x + v7.x));
        a1 += ((v0.y + v1.y) + (v2.y + v3.y)) + ((v4.y + v5.y) + (v6.y + v7.y));
    }
    for (; k < end; k++) {
        float2 v = __half22float2(h1[g_adj[k] * 8 + ln]);
        a0 += v.x; a1 += v.y;
    }
    float2 self = __half22float2(h1[node * 8 + ln]);
    float dv = g_dinv[node];
    float o0 = dv * (a0 + self.x);
    float o1 = dv * (a1 + self.y);
    int f0 = ln * 2, f1 = f0 + 1;
    float v0 = fmaxf(o0 + b1[f0], 0.0f);
    float v1 = fmaxf(o1 + b1[f1], 0.0f);
    float c0 = fmaf(v0, W2[f0 * 2 + 0], v1 * W2[f1 * 2 + 0]);
    float c1 = fmaf(v0, W2[f0 * 2 + 1], v1 * W2[f1 * 2 + 1]);
    #pragma unroll
    for (int m = 4; m >= 1; m >>= 1) {
        c0 += __shfl_xor_sync(0xffffffffu, c0, m, 8);
        c1 += __shfl_xor_sync(0xffffffffu, c1, m, 8);
    }
    if (ln == 0) ((float2*)g_h2s)[node] = make_float2(c0 * dv, c1 * dv);
}

// ---------------- Aggregation 2 + bias + log_softmax ------------------------
__global__ void k_agg2g(const float* __restrict__ b2, float* __restrict__ out) {
    int i = blockIdx.x * blockDim.x + threadIdx.x;
    if (i >= NN) return;
    int beg = g_beg[i];
    int end = beg + g_cnt[i];
    float a0 = 0.0f, a1 = 0.0f;
    const float2* h2 = (const float2*)g_h2s;
    int k = beg;
    for (; k + 8 <= end; k += 8) {
        float2 v0 = h2[g_adj[k]];
        float2 v1 = h2[g_adj[k + 1]];
        float2 v2 = h2[g_adj[k + 2]];
        float2 v3 = h2[g_adj[k + 3]];
        float2 v4 = h2[g_adj[k + 4]];
        float2 v5 = h2[g_adj[k + 5]];
        float2 v6 = h2[g_adj[k + 6]];
        float2 v7 = h2[g_adj[k + 7]];
        a0 += ((v0.x + v1.x) + (v2.x + v3.x)) + ((v4.x + v5.x) + (v6.x + v7.x));
        a1 += ((v0.y + v1.y) + (v2.y + v3.y)) + ((v4.y + v5.y) + (v6.y + v7.y));
    }
    for (; k < end; k++) { float2 v = h2[g_adj[k]]; a0 += v.x; a1 += v.y; }
    float dv = g_dinv[i];
    float2 self = h2[i];
    float A = dv * (a0 + self.x) + b2[0];
    float B = dv * (a1 + self.y) + b2[1];
    float m = fmaxf(A, B);
    float lse = m + logf(expf(A - m) + expf(B - m));
    ((float2*)out)[i] = make_float2(A - lse, B - lse);
}

// ---------------- launch ----------------------------------------------------

extern "C" void kernel_launch(void* const* d_in, const int* in_sizes, int n_in,
                              void* d_out, int out_size) {
    const float* x  = (const float*)d_in[0];
    const int*   ei = (const int*)  d_in[1];
    const float* W1 = (const float*)d_in[2];
    const float* b1 = (const float*)d_in[3];
    const float* W2 = (const float*)d_in[4];
    const float* b2 = (const float*)d_in[5];
    float* out = (float*)d_out;

    int E = in_sizes[1] / 2;
    const int* src = ei;
    const int* dst = ei + E;

    void* cnt_ptr = 0;
    cudaGetSymbolAddress(&cnt_ptr, g_cnt);
    cudaMemsetAsync(cnt_ptr, 0, NN * sizeof(int), 0);

    int nt4 = (E + 3) / 4;
    k_count  <<<(nt4 + 255) / 256, 256>>>(dst, E);
    k_offsets<<<NB_OFF, OFF_BLK>>>();
    k_scatter<<<(nt4 + 255) / 256, 256>>>(src, dst, E);
    k_gemm1  <<<(NN + 127) / 128, 128>>>(x, W1);
    k_agg1f  <<<(NN + 31) / 32, 256>>>(b1, W2);
    k_agg2g  <<<(NN + 255) / 256, 256>>>(b2, out);
}